// round 13
// baseline (speedup 1.0000x reference)
#include <cuda_runtime.h>
#include <cuda_fp16.h>
#include <mma.h>
#include <math.h>
#include <stdint.h>

using namespace nvcuda;

#define NB    4096
#define NFG_  1024
#define NFP_  256
#define NFR_  256
#define NG_   4
#define FPPD  1280
#define THR2  302.76f                      // (0.2*87)^2
#define SIMSCALE 0.044194173824159216f     // 1/sqrt(512)

// ---------------- device scratch (static, allocation-free) ----------------
__device__ float  g_foot[NB * 2];
__device__ __half g_fpp_h [(size_t)NB * FPPD];
__device__ __half g_thW_h [(size_t)NG_ * FPPD * NFR_];
__device__ __half g_phW_h [(size_t)NG_ * FPPD * NFR_];
__device__ __half g_gwW_h [(size_t)NG_ * NFG_ * NFG_];
__device__ __half g_ft_h  [(size_t)NB * NFG_];
__device__ __half g_theta_h[(size_t)NG_ * NB * NFR_];
__device__ __half g_phi_h  [(size_t)NG_ * NB * NFR_];
__device__ __half g_A_h  [(size_t)NG_ * NB * NB];         // sim fp16 -> A in place
__device__ __half g_agg_h[(size_t)NG_ * NB * NFG_];
__device__ __half g_outp_h[(size_t)NG_ * NB * NFG_];      // out fp16 (pre-LN)

// ---------------- cp.async helpers ----------------
__device__ __forceinline__ void cp_async16(void* smem_dst, const void* gmem_src) {
    unsigned s = (unsigned)__cvta_generic_to_shared(smem_dst);
    asm volatile("cp.async.cg.shared.global [%0], [%1], 16;\n" :: "r"(s), "l"(gmem_src));
}
#define CP_COMMIT() asm volatile("cp.async.commit_group;\n" ::: "memory")

// ---------------- foot points ----------------
__global__ void foot_kernel(const float* __restrict__ boxes, float* __restrict__ foot) {
    int n = blockIdx.x * 256 + threadIdx.x;
    if (n < NB) {
        foot[2 * n]     = (boxes[4 * n + 0] + boxes[4 * n + 2]) * 0.5f;
        foot[2 * n + 1] = boxes[4 * n + 3];
    }
}

// ---------------- fpp (fp16) = [sincos_emb(foot,256) | feats] ----------------
__global__ void fpp_kernel(const float* __restrict__ feats,
                           const float* __restrict__ foot,
                           __half* __restrict__ fpp) {
    long long idx = (long long)blockIdx.x * 256 + threadIdx.x;
    if (idx >= (long long)NB * FPPD) return;
    int n = (int)(idx / FPPD);
    int j = (int)(idx % FPPD);
    float v;
    if (j < NFP_) {
        int coord = j / 128;
        int jj = j % 128;
        int i = jj & 63;
        bool is_cos = jj >= 64;
        float freq = expf(-(float)i * 0.14391157750382243f);  // 10000^(-i/64)
        float ang = foot[2 * n + coord] * freq;
        v = is_cos ? cosf(ang) : sinf(ang);
    } else {
        v = feats[(long long)n * NFG_ + (j - NFP_)];
    }
    fpp[idx] = __float2half(v);
}

// ---------------- elementwise fp32 -> fp16 ----------------
__global__ void conv_kernel(const float* __restrict__ in, __half* __restrict__ out, long long n) {
    long long i = ((long long)blockIdx.x * 256 + threadIdx.x) * 4;
    if (i >= n) return;
    float4 v = *(const float4*)(in + i);
    __half2 h0 = __floats2half2_rn(v.x, v.y);
    __half2 h1 = __floats2half2_rn(v.z, v.w);
    *(uint2*)(out + i) = make_uint2(*(uint32_t*)&h0, *(uint32_t*)&h1);
}

// ========== fp16 wmma GEMM, 128x256 block, BK=32, 5-stage, 512 threads =======
// 16 warps as 2x8, warp tile 64x32 (4x2 frags, identical per-warp regs to R5).
// One __syncthreads per K-iteration; up to 4 tiles in flight.
// TRANSB=0: B is [K,N] row-major; TRANSB=1: B is [N,K] row-major (A @ B^T).
// Output fp16 via register fragment convert. BIAS=1: +fp32 per-column bias.
#define GBM 128
#define GBN 256
#define GBK 32
#define APAD 40     // halves per A row (32 + 8)
#define BPAD 264    // halves per B row, nontrans (256 + 8)
#define NSTG 5
#define A_HV (GBM * APAD)        // 5120 halves per stage
#define BT_HV (GBN * APAD)       // 10240 (trans: 256 rows x 40)
#define BNT_HV (GBK * BPAD)      // 8448 (non-trans: 32 rows x 264)
#define SMEM_T  ((NSTG * (A_HV + BT_HV)) * 2)    // 153600 B
#define SMEM_NT ((NSTG * (A_HV + BNT_HV)) * 2)   // 135680 B

template<int TRANSB, int BIAS>
__global__ __launch_bounds__(512, 1)
void hgemm_kernel(const __half* __restrict__ Aall, const __half* __restrict__ Ball,
                  __half* __restrict__ Chall, const float* __restrict__ bias,
                  int M, int N, int K,
                  long long sA, long long sB, long long sC)
{
    extern __shared__ char dsm[];
    __half* As = (__half*)dsm;                       // NSTG x A_HV
    __half* Bs = (__half*)dsm + NSTG * A_HV;         // NSTG x B tile
    const int BHV = TRANSB ? BT_HV : BNT_HV;

    int g = blockIdx.z;
    const __half* A = Aall + (long long)g * sA;
    const __half* B = Ball + (long long)g * sB;

    int tid = threadIdx.x;
    int wid = tid >> 5;
    int wr = wid >> 3;      // 0..1  -> 64-row group
    int wc = wid & 7;       // 0..7  -> 32-col group
    int rowBase = blockIdx.y * GBM;
    int colBase = blockIdx.x * GBN;

    using FragA  = wmma::fragment<wmma::matrix_a, 16, 16, 16, __half, wmma::row_major>;
    using FragBr = wmma::fragment<wmma::matrix_b, 16, 16, 16, __half, wmma::row_major>;
    using FragBc = wmma::fragment<wmma::matrix_b, 16, 16, 16, __half, wmma::col_major>;
    using FragC  = wmma::fragment<wmma::accumulator, 16, 16, 16, float>;
    using FragCh = wmma::fragment<wmma::accumulator, 16, 16, 16, __half>;

    FragC acc[4][2];
    #pragma unroll
    for (int i = 0; i < 4; i++)
        #pragma unroll
        for (int j = 0; j < 2; j++)
            wmma::fill_fragment(acc[i][j], 0.0f);

    int KT = K / GBK;

    // A tile: 128x32 halves = 512 16B-units -> 1/thread.
    // B tile: 1024 16B-units (either layout) -> 2/thread.
    #define ISSUE(kt, buf) {                                                              \
        int k0 = (kt) * GBK;                                                              \
        {                                                                                  \
            int u = tid;                                                                   \
            int ar = u >> 2, ac = (u & 3) * 8;                                             \
            cp_async16(As + (buf) * A_HV + ar * APAD + ac,                                 \
                       A + (long long)(rowBase + ar) * K + k0 + ac);                       \
        }                                                                                  \
        _Pragma("unroll")                                                                  \
        for (int q = 0; q < 2; q++) {                                                      \
            int u = tid * 2 + q;                                                           \
            if (TRANSB) {                                                                  \
                int br = u >> 2, bc = (u & 3) * 8;                                         \
                cp_async16(Bs + (buf) * BHV + br * APAD + bc,                              \
                           B + (long long)(colBase + br) * K + k0 + bc);                   \
            } else {                                                                       \
                int br = u >> 5, bc = (u & 31) * 8;                                        \
                cp_async16(Bs + (buf) * BHV + br * BPAD + bc,                              \
                           B + (long long)(k0 + br) * N + colBase + bc);                   \
            }                                                                              \
        }                                                                                  \
    }

    // prologue: 4 tiles in flight (all call sites have KT >= 8)
    ISSUE(0, 0); CP_COMMIT();
    ISSUE(1, 1); CP_COMMIT();
    ISSUE(2, 2); CP_COMMIT();
    ISSUE(3, 3); CP_COMMIT();

    int buf = 0;
    for (int kt = 0; kt < KT; kt++) {
        int rem = KT - kt - 1;
        if (rem >= 3)
            asm volatile("cp.async.wait_group 3;\n" ::: "memory");
        else if (rem == 2)
            asm volatile("cp.async.wait_group 2;\n" ::: "memory");
        else if (rem == 1)
            asm volatile("cp.async.wait_group 1;\n" ::: "memory");
        else
            asm volatile("cp.async.wait_group 0;\n" ::: "memory");
        __syncthreads();   // tile kt visible; all warps done with tile kt-1

        if (kt + 4 < KT) {
            int nb = buf + 4; if (nb >= NSTG) nb -= NSTG;
            ISSUE(kt + 4, nb); CP_COMMIT();
        }

        #pragma unroll
        for (int ks = 0; ks < 2; ks++) {
            FragA af[4];
            #pragma unroll
            for (int i = 0; i < 4; i++)
                wmma::load_matrix_sync(af[i],
                    As + buf * A_HV + (wr * 64 + i * 16) * APAD + ks * 16, APAD);
            if (TRANSB) {
                FragBc bf[2];
                #pragma unroll
                for (int j = 0; j < 2; j++)
                    wmma::load_matrix_sync(bf[j],
                        Bs + buf * BHV + (wc * 32 + j * 16) * APAD + ks * 16, APAD);
                #pragma unroll
                for (int i = 0; i < 4; i++)
                    #pragma unroll
                    for (int j = 0; j < 2; j++)
                        wmma::mma_sync(acc[i][j], af[i], bf[j], acc[i][j]);
            } else {
                FragBr bf[2];
                #pragma unroll
                for (int j = 0; j < 2; j++)
                    wmma::load_matrix_sync(bf[j],
                        Bs + buf * BHV + (ks * 16) * BPAD + wc * 32 + j * 16, BPAD);
                #pragma unroll
                for (int i = 0; i < 4; i++)
                    #pragma unroll
                    for (int j = 0; j < 2; j++)
                        wmma::mma_sync(acc[i][j], af[i], bf[j], acc[i][j]);
            }
        }
        if (++buf == NSTG) buf = 0;
    }
    #undef ISSUE

    if (BIAS) {
        // stage bias[colBase..colBase+255] replicated over 16 rows in (dead) smem,
        // load as accumulator fragment, add elementwise (same-layout FragC mapping).
        __syncthreads();
        float* bs = (float*)dsm;                 // 16 rows x 264 pitch
        if (tid < GBN) {
            float bv = bias[(long long)g * N + colBase + tid];
            #pragma unroll
            for (int r = 0; r < 16; r++) bs[r * 264 + tid] = bv;
        }
        __syncthreads();
        FragC bfr[2];
        #pragma unroll
        for (int j = 0; j < 2; j++)
            wmma::load_matrix_sync(bfr[j], bs + wc * 32 + j * 16, 264, wmma::mem_row_major);
        #pragma unroll
        for (int i = 0; i < 4; i++)
            #pragma unroll
            for (int j = 0; j < 2; j++)
                #pragma unroll
                for (int t = 0; t < bfr[0].num_elements; t++)
                    acc[i][j].x[t] += bfr[j].x[t];
    }

    // register-resident fp32 -> fp16 fragment conversion, direct store
    __half* Ch = Chall + (long long)g * sC;
    #pragma unroll
    for (int i = 0; i < 4; i++)
        #pragma unroll
        for (int j = 0; j < 2; j++) {
            FragCh hc;
            #pragma unroll
            for (int t = 0; t < hc.num_elements; t++)
                hc.x[t] = __float2half(acc[i][j].x[t]);
            wmma::store_matrix_sync(
                Ch + (long long)(rowBase + wr * 64 + i * 16) * N + colBase + wc * 32 + j * 16,
                hc, N, wmma::mem_row_major);
        }
}

// ------- fused scale + mask + softmax over all 4 g + final_graph, per row -------
__global__ void softmax_fg_kernel(__half* __restrict__ Ah, const float* __restrict__ foot,
                                  float* __restrict__ fg) {
    int n = blockIdx.x;
    int tid = threadIdx.x;
    __shared__ float red[256];
    float frx = foot[2 * n], fry = foot[2 * n + 1];

    unsigned mask = 0;
    #pragma unroll
    for (int i = 0; i < 8; i++) {
        int c = 2 * (tid + i * 256);
        float dx0 = frx - foot[2 * c],     dy0 = fry - foot[2 * c + 1];
        float dx1 = frx - foot[2 * c + 2], dy1 = fry - foot[2 * c + 3];
        if (dx0 * dx0 + dy0 * dy0 > THR2) mask |= (1u << (2 * i));
        if (dx1 * dx1 + dy1 * dy1 > THR2) mask |= (1u << (2 * i + 1));
    }

    float fgx[8], fgy[8];
    #pragma unroll
    for (int i = 0; i < 8; i++) { fgx[i] = 0.f; fgy[i] = 0.f; }

    for (int g = 0; g < NG_; g++) {
        __half2* row2 = (__half2*)(Ah + ((long long)g * NB + n) * NB);
        float v0[8], v1[8];
        float m = -INFINITY;
        #pragma unroll
        for (int i = 0; i < 8; i++) {
            float2 s = __half22float2(row2[tid + i * 256]);
            v0[i] = (mask & (1u << (2 * i)))     ? -INFINITY : s.x * SIMSCALE;
            v1[i] = (mask & (1u << (2 * i + 1))) ? -INFINITY : s.y * SIMSCALE;
            m = fmaxf(m, fmaxf(v0[i], v1[i]));
        }
        red[tid] = m; __syncthreads();
        for (int s = 128; s > 0; s >>= 1) { if (tid < s) red[tid] = fmaxf(red[tid], red[tid + s]); __syncthreads(); }
        m = red[0]; __syncthreads();
        float sum = 0.0f;
        #pragma unroll
        for (int i = 0; i < 8; i++) {
            v0[i] = __expf(v0[i] - m); v1[i] = __expf(v1[i] - m);
            sum += v0[i] + v1[i];
        }
        red[tid] = sum; __syncthreads();
        for (int s = 128; s > 0; s >>= 1) { if (tid < s) red[tid] += red[tid + s]; __syncthreads(); }
        float inv = 1.0f / red[0];
        __syncthreads();
        #pragma unroll
        for (int i = 0; i < 8; i++) {
            float a0 = v0[i] * inv, a1 = v1[i] * inv;
            row2[tid + i * 256] = __floats2half2_rn(a0, a1);
            fgx[i] += a0; fgy[i] += a1;
        }
    }

    float2* fg2 = (float2*)(fg + (long long)n * NB);
    #pragma unroll
    for (int i = 0; i < 8; i++) {
        float2 r;
        r.x = fminf(0.25f * fgx[i], 1.0f);
        r.y = fminf(0.25f * fgy[i], 1.0f);
        fg2[tid + i * 256] = r;
    }
}

// ---------------- LayerNorm + ReLU + sum over g (fp16 input) ----------------
__global__ void ln_kernel(const __half* __restrict__ outp,
                          const float* __restrict__ gamma,
                          const float* __restrict__ beta,
                          float* __restrict__ out) {
    int n = blockIdx.x;
    int tid = threadIdx.x;  // 256
    __shared__ float red[256];
    float accum[4] = {0.f, 0.f, 0.f, 0.f};
    for (int g = 0; g < NG_; g++) {
        const __half2* row2 = (const __half2*)(outp + ((long long)g * NB + n) * NFG_);
        float v[4];
        {
            float2 a = __half22float2(row2[tid]);
            float2 b = __half22float2(row2[tid + 256]);
            v[0] = a.x; v[1] = a.y; v[2] = b.x; v[3] = b.y;
        }
        float s = v[0] + v[1] + v[2] + v[3];
        red[tid] = s; __syncthreads();
        for (int st = 128; st > 0; st >>= 1) { if (tid < st) red[tid] += red[tid + st]; __syncthreads(); }
        float mean = red[0] * (1.0f / NFG_); __syncthreads();
        float s2 = 0.0f;
        #pragma unroll
        for (int i = 0; i < 4; i++) { float d = v[i] - mean; s2 += d * d; }
        red[tid] = s2; __syncthreads();
        for (int st = 128; st > 0; st >>= 1) { if (tid < st) red[tid] += red[tid + st]; __syncthreads(); }
        float inv = rsqrtf(red[0] * (1.0f / NFG_) + 1e-5f);
        __syncthreads();
        {
            int c0 = 2 * tid, c1 = 2 * (tid + 256);
            const float* ga = gamma + g * NFG_;
            const float* be = beta + g * NFG_;
            accum[0] += fmaxf((v[0] - mean) * inv * ga[c0]     + be[c0],     0.0f);
            accum[1] += fmaxf((v[1] - mean) * inv * ga[c0 + 1] + be[c0 + 1], 0.0f);
            accum[2] += fmaxf((v[2] - mean) * inv * ga[c1]     + be[c1],     0.0f);
            accum[3] += fmaxf((v[3] - mean) * inv * ga[c1 + 1] + be[c1 + 1], 0.0f);
        }
    }
    float* orow = out + (long long)n * NFG_;
    *(float2*)(orow + 2 * tid)         = make_float2(accum[0], accum[1]);
    *(float2*)(orow + 2 * (tid + 256)) = make_float2(accum[2], accum[3]);
}

// ======================= launch =======================
extern "C" void kernel_launch(void* const* d_in, const int* in_sizes, int n_in,
                              void* d_out, int out_size) {
    const float* feats   = (const float*)d_in[0];
    const float* boxes   = (const float*)d_in[1];
    const float* theta_w = (const float*)d_in[2];
    const float* theta_b = (const float*)d_in[3];
    const float* phi_w   = (const float*)d_in[4];
    const float* phi_b   = (const float*)d_in[5];
    const float* gcn_w   = (const float*)d_in[6];
    const float* ln_g    = (const float*)d_in[7];
    const float* ln_b    = (const float*)d_in[8];
    float* out = (float*)d_out;   // [4096*1024] out ++ [4096*4096] final_graph

    float *p_foot;
    __half *p_fpp, *p_thW, *p_phW, *p_gwW, *p_ft, *p_theta, *p_phi, *p_Ah, *p_agg, *p_outp;
    cudaGetSymbolAddress((void**)&p_foot, g_foot);
    cudaGetSymbolAddress((void**)&p_fpp,  g_fpp_h);
    cudaGetSymbolAddress((void**)&p_thW,  g_thW_h);
    cudaGetSymbolAddress((void**)&p_phW,  g_phW_h);
    cudaGetSymbolAddress((void**)&p_gwW,  g_gwW_h);
    cudaGetSymbolAddress((void**)&p_ft,   g_ft_h);
    cudaGetSymbolAddress((void**)&p_theta, g_theta_h);
    cudaGetSymbolAddress((void**)&p_phi,  g_phi_h);
    cudaGetSymbolAddress((void**)&p_Ah,   g_A_h);
    cudaGetSymbolAddress((void**)&p_agg,  g_agg_h);
    cudaGetSymbolAddress((void**)&p_outp, g_outp_h);

    cudaFuncSetAttribute(hgemm_kernel<0,1>, cudaFuncAttributeMaxDynamicSharedMemorySize, SMEM_NT);
    cudaFuncSetAttribute(hgemm_kernel<0,0>, cudaFuncAttributeMaxDynamicSharedMemorySize, SMEM_NT);
    cudaFuncSetAttribute(hgemm_kernel<1,0>, cudaFuncAttributeMaxDynamicSharedMemorySize, SMEM_T);

    // 1) foot + fpp(fp16)
    foot_kernel<<<(NB + 255) / 256, 256>>>(boxes, p_foot);
    long long fppN = (long long)NB * FPPD;
    fpp_kernel<<<(unsigned)((fppN + 255) / 256), 256>>>(feats, p_foot, p_fpp);

    // 2) fp16 operand conversions
    {
        long long nw = (long long)NG_ * FPPD * NFR_;
        conv_kernel<<<(unsigned)(nw / 4 / 256), 256>>>(theta_w, p_thW, nw);
        conv_kernel<<<(unsigned)(nw / 4 / 256), 256>>>(phi_w, p_phW, nw);
        long long ng = (long long)NG_ * NFG_ * NFG_;
        conv_kernel<<<(unsigned)(ng / 4 / 256), 256>>>(gcn_w, p_gwW, ng);
        long long nf = (long long)NB * NFG_;
        conv_kernel<<<(unsigned)(nf / 4 / 256), 256>>>(feats, p_ft, nf);
    }

    // 3) theta/phi GEMMs -> fp16 with fused bias epilogue (N=256 = one tile col)
    {
        dim3 grid(NFR_ / GBN, NB / GBM, NG_);   // (1, 32, 4)
        hgemm_kernel<0,1><<<grid, 512, SMEM_NT>>>(p_fpp, p_thW, p_theta, theta_b,
                                                  NB, NFR_, FPPD,
                                                  0, (long long)FPPD * NFR_, (long long)NB * NFR_);
        hgemm_kernel<0,1><<<grid, 512, SMEM_NT>>>(p_fpp, p_phW, p_phi, phi_b,
                                                  NB, NFR_, FPPD,
                                                  0, (long long)FPPD * NFR_, (long long)NB * NFR_);
    }

    // 4) sim = theta @ phi^T -> fp16 directly into A buffer
    {
        dim3 grid(NB / GBN, NB / GBM, NG_);     // (16, 32, 4)
        hgemm_kernel<1,0><<<grid, 512, SMEM_T>>>(p_theta, p_phi, p_Ah, nullptr,
                                                 NB, NB, NFR_,
                                                 (long long)NB * NFR_, (long long)NB * NFR_,
                                                 (long long)NB * NB);
    }

    // 5) softmax over all g + final_graph (fused), fp16 A in-place
    softmax_fg_kernel<<<NB, 256>>>(p_Ah, p_foot, out + (long long)NB * NFG_);

    // 6) agg = A @ feats -> fp16
    {
        dim3 grid(NFG_ / GBN, NB / GBM, NG_);   // (4, 32, 4)
        hgemm_kernel<0,0><<<grid, 512, SMEM_NT>>>(p_Ah, p_ft, p_agg, nullptr,
                                                  NB, NFG_, NB,
                                                  (long long)NB * NB, 0, (long long)NB * NFG_);
    }

    // 7) outp = agg @ gcn_w -> fp16
    {
        dim3 grid(NFG_ / GBN, NB / GBM, NG_);   // (4, 32, 4)
        hgemm_kernel<0,0><<<grid, 512, SMEM_NT>>>(p_agg, p_gwW, p_outp, nullptr,
                                                  NB, NFG_, NFG_,
                                                  (long long)NB * NFG_, (long long)NFG_ * NFG_,
                                                  (long long)NB * NFG_);
    }

    // 8) LN + ReLU + sum over g
    ln_kernel<<<NB, 256>>>(p_outp, ln_g, ln_b, out);
}

// round 14
// speedup vs baseline: 1.1356x; 1.1356x over previous
#include <cuda_runtime.h>
#include <cuda_fp16.h>
#include <mma.h>
#include <math.h>
#include <stdint.h>

using namespace nvcuda;

#define NB    4096
#define NFG_  1024
#define NFP_  256
#define NFR_  256
#define NG_   4
#define FPPD  1280
#define THR2  302.76f                      // (0.2*87)^2
#define SIMSCALE 0.044194173824159216f     // 1/sqrt(512)

// ---------------- device scratch (static, allocation-free) ----------------
__device__ float  g_foot[NB * 2];
__device__ __half g_fpp_h [(size_t)NB * FPPD];
__device__ __half g_thW_h [(size_t)NG_ * FPPD * NFR_];
__device__ __half g_phW_h [(size_t)NG_ * FPPD * NFR_];
__device__ __half g_gwW_h [(size_t)NG_ * NFG_ * NFG_];
__device__ __half g_ft_h  [(size_t)NB * NFG_];
__device__ __half g_theta_h[(size_t)NG_ * NB * NFR_];
__device__ __half g_phi_h  [(size_t)NG_ * NB * NFR_];
__device__ __half g_A_h  [(size_t)NG_ * NB * NB];         // sim fp16 -> A in place
__device__ __half g_agg_h[(size_t)NG_ * NB * NFG_];
__device__ __half g_outp_h[(size_t)NG_ * NB * NFG_];      // out fp16 (pre-LN)

// ---------------- cp.async helpers ----------------
__device__ __forceinline__ void cp_async16(void* smem_dst, const void* gmem_src) {
    unsigned s = (unsigned)__cvta_generic_to_shared(smem_dst);
    asm volatile("cp.async.cg.shared.global [%0], [%1], 16;\n" :: "r"(s), "l"(gmem_src));
}
#define CP_COMMIT() asm volatile("cp.async.commit_group;\n" ::: "memory")

// ---------------- block reduction: warp shuffle + 1 smem stage (2 syncs) -----
// red must be float[8]; result broadcast to all threads. OP: 0=max, 1=sum.
template<int OP>
__device__ __forceinline__ float block_reduce_256(float v, float* red8, int tid) {
    #pragma unroll
    for (int o = 16; o > 0; o >>= 1) {
        float w = __shfl_xor_sync(0xFFFFFFFFu, v, o);
        v = OP ? (v + w) : fmaxf(v, w);
    }
    if ((tid & 31) == 0) red8[tid >> 5] = v;
    __syncthreads();
    float r = red8[0];
    #pragma unroll
    for (int k = 1; k < 8; k++) r = OP ? (r + red8[k]) : fmaxf(r, red8[k]);
    __syncthreads();
    return r;
}

// ---------------- foot points ----------------
__global__ void foot_kernel(const float* __restrict__ boxes, float* __restrict__ foot) {
    int n = blockIdx.x * 256 + threadIdx.x;
    if (n < NB) {
        foot[2 * n]     = (boxes[4 * n + 0] + boxes[4 * n + 2]) * 0.5f;
        foot[2 * n + 1] = boxes[4 * n + 3];
    }
}

// ---------------- fpp (fp16) = [sincos_emb(foot,256) | feats] ----------------
__global__ void fpp_kernel(const float* __restrict__ feats,
                           const float* __restrict__ foot,
                           __half* __restrict__ fpp) {
    long long idx = (long long)blockIdx.x * 256 + threadIdx.x;
    if (idx >= (long long)NB * FPPD) return;
    int n = (int)(idx / FPPD);
    int j = (int)(idx % FPPD);
    float v;
    if (j < NFP_) {
        int coord = j / 128;
        int jj = j % 128;
        int i = jj & 63;
        bool is_cos = jj >= 64;
        float freq = expf(-(float)i * 0.14391157750382243f);  // 10000^(-i/64)
        float ang = foot[2 * n + coord] * freq;
        v = is_cos ? cosf(ang) : sinf(ang);
    } else {
        v = feats[(long long)n * NFG_ + (j - NFP_)];
    }
    fpp[idx] = __float2half(v);
}

// ---------------- elementwise fp32 -> fp16 ----------------
__global__ void conv_kernel(const float* __restrict__ in, __half* __restrict__ out, long long n) {
    long long i = ((long long)blockIdx.x * 256 + threadIdx.x) * 4;
    if (i >= n) return;
    float4 v = *(const float4*)(in + i);
    __half2 h0 = __floats2half2_rn(v.x, v.y);
    __half2 h1 = __floats2half2_rn(v.z, v.w);
    *(uint2*)(out + i) = make_uint2(*(uint32_t*)&h0, *(uint32_t*)&h1);
}

// ======================= fp16 wmma GEMM, 128x128, BK=32, 5-stage (R12) ========
// 8 warps 2x4, warp tile 64x32 (4x2 frags), dynamic smem (5 buffers).
// One __syncthreads per K-iteration; up to 4 tiles in flight.
// TRANSB=0: B is [K,N] row-major; TRANSB=1: B is [N,K] row-major (A @ B^T).
// Output fp16 via register fragment convert. BIAS=1: +fp32 per-column bias.
#define GBM 128
#define GBN 128
#define GBK 32
#define APAD 40     // halves per A row (32 + 8)
#define BPAD 136    // halves per B row, nontrans (128 + 8)
#define NSTG 5
#define A_HV (GBM * APAD)        // 5120 halves per stage
#define BT_HV (GBN * APAD)       // 5120 (trans)
#define BNT_HV (GBK * BPAD)      // 4352 (non-trans)
#define SMEM_T  ((NSTG * (A_HV + BT_HV)) * 2)    // 102400 B
#define SMEM_NT ((NSTG * (A_HV + BNT_HV)) * 2)   // 94720 B

template<int TRANSB, int BIAS>
__global__ __launch_bounds__(256, 2)
void hgemm_kernel(const __half* __restrict__ Aall, const __half* __restrict__ Ball,
                  __half* __restrict__ Chall, const float* __restrict__ bias,
                  int M, int N, int K,
                  long long sA, long long sB, long long sC)
{
    extern __shared__ char dsm[];
    __half* As = (__half*)dsm;                       // NSTG x A_HV
    __half* Bs = (__half*)dsm + NSTG * A_HV;         // NSTG x B tile
    const int BHV = TRANSB ? BT_HV : BNT_HV;

    int g = blockIdx.z;
    const __half* A = Aall + (long long)g * sA;
    const __half* B = Ball + (long long)g * sB;

    int tid = threadIdx.x;
    int wid = tid >> 5;
    int wr = wid >> 2;      // 0..1  -> 64-row group
    int wc = wid & 3;       // 0..3  -> 32-col group
    int rowBase = blockIdx.y * GBM;
    int colBase = blockIdx.x * GBN;

    using FragA  = wmma::fragment<wmma::matrix_a, 16, 16, 16, __half, wmma::row_major>;
    using FragBr = wmma::fragment<wmma::matrix_b, 16, 16, 16, __half, wmma::row_major>;
    using FragBc = wmma::fragment<wmma::matrix_b, 16, 16, 16, __half, wmma::col_major>;
    using FragC  = wmma::fragment<wmma::accumulator, 16, 16, 16, float>;
    using FragCh = wmma::fragment<wmma::accumulator, 16, 16, 16, __half>;

    FragC acc[4][2];
    #pragma unroll
    for (int i = 0; i < 4; i++)
        #pragma unroll
        for (int j = 0; j < 2; j++)
            wmma::fill_fragment(acc[i][j], 0.0f);

    int KT = K / GBK;
    int u0 = tid * 2;

    #define ISSUE(kt, buf) {                                                              \
        int k0 = (kt) * GBK;                                                              \
        _Pragma("unroll")                                                                 \
        for (int q = 0; q < 2; q++) {                                                     \
            int u = u0 + q;                                                               \
            int ar = u >> 2, ac = (u & 3) * 8;                                            \
            cp_async16(As + (buf) * A_HV + ar * APAD + ac,                                \
                       A + (long long)(rowBase + ar) * K + k0 + ac);                      \
            if (TRANSB) {                                                                 \
                int br = u >> 2, bc = (u & 3) * 8;                                        \
                cp_async16(Bs + (buf) * BHV + br * APAD + bc,                             \
                           B + (long long)(colBase + br) * K + k0 + bc);                  \
            } else {                                                                      \
                int br = u >> 4, bc = (u & 15) * 8;                                       \
                cp_async16(Bs + (buf) * BHV + br * BPAD + bc,                             \
                           B + (long long)(k0 + br) * N + colBase + bc);                  \
            }                                                                             \
        }                                                                                 \
    }

    // prologue: 4 tiles in flight (all call sites have KT >= 8)
    ISSUE(0, 0); CP_COMMIT();
    ISSUE(1, 1); CP_COMMIT();
    ISSUE(2, 2); CP_COMMIT();
    ISSUE(3, 3); CP_COMMIT();

    int buf = 0;
    for (int kt = 0; kt < KT; kt++) {
        int rem = KT - kt - 1;
        if (rem >= 3)
            asm volatile("cp.async.wait_group 3;\n" ::: "memory");
        else if (rem == 2)
            asm volatile("cp.async.wait_group 2;\n" ::: "memory");
        else if (rem == 1)
            asm volatile("cp.async.wait_group 1;\n" ::: "memory");
        else
            asm volatile("cp.async.wait_group 0;\n" ::: "memory");
        __syncthreads();   // tile kt visible; all warps done with tile kt-1

        if (kt + 4 < KT) {
            int nb = buf + 4; if (nb >= NSTG) nb -= NSTG;
            ISSUE(kt + 4, nb); CP_COMMIT();
        }

        #pragma unroll
        for (int ks = 0; ks < 2; ks++) {
            FragA af[4];
            #pragma unroll
            for (int i = 0; i < 4; i++)
                wmma::load_matrix_sync(af[i],
                    As + buf * A_HV + (wr * 64 + i * 16) * APAD + ks * 16, APAD);
            if (TRANSB) {
                FragBc bf[2];
                #pragma unroll
                for (int j = 0; j < 2; j++)
                    wmma::load_matrix_sync(bf[j],
                        Bs + buf * BHV + (wc * 32 + j * 16) * APAD + ks * 16, APAD);
                #pragma unroll
                for (int i = 0; i < 4; i++)
                    #pragma unroll
                    for (int j = 0; j < 2; j++)
                        wmma::mma_sync(acc[i][j], af[i], bf[j], acc[i][j]);
            } else {
                FragBr bf[2];
                #pragma unroll
                for (int j = 0; j < 2; j++)
                    wmma::load_matrix_sync(bf[j],
                        Bs + buf * BHV + (ks * 16) * BPAD + wc * 32 + j * 16, BPAD);
                #pragma unroll
                for (int i = 0; i < 4; i++)
                    #pragma unroll
                    for (int j = 0; j < 2; j++)
                        wmma::mma_sync(acc[i][j], af[i], bf[j], acc[i][j]);
            }
        }
        if (++buf == NSTG) buf = 0;
    }
    #undef ISSUE

    if (BIAS) {
        // stage bias[colBase..colBase+127] replicated over 16 rows in (dead) smem,
        // load as accumulator fragment, add elementwise (same-layout FragC mapping).
        __syncthreads();
        float* bs = (float*)dsm;                 // 16 rows x 136 pitch
        if (tid < GBN) {
            float bv = bias[(long long)g * N + colBase + tid];
            #pragma unroll
            for (int r = 0; r < 16; r++) bs[r * 136 + tid] = bv;
        }
        __syncthreads();
        FragC bfr[2];
        #pragma unroll
        for (int j = 0; j < 2; j++)
            wmma::load_matrix_sync(bfr[j], bs + wc * 32 + j * 16, 136, wmma::mem_row_major);
        #pragma unroll
        for (int i = 0; i < 4; i++)
            #pragma unroll
            for (int j = 0; j < 2; j++)
                #pragma unroll
                for (int t = 0; t < bfr[0].num_elements; t++)
                    acc[i][j].x[t] += bfr[j].x[t];
    }

    // register-resident fp32 -> fp16 fragment conversion, direct store
    __half* Ch = Chall + (long long)g * sC;
    #pragma unroll
    for (int i = 0; i < 4; i++)
        #pragma unroll
        for (int j = 0; j < 2; j++) {
            FragCh hc;
            #pragma unroll
            for (int t = 0; t < hc.num_elements; t++)
                hc.x[t] = __float2half(acc[i][j].x[t]);
            wmma::store_matrix_sync(
                Ch + (long long)(rowBase + wr * 64 + i * 16) * N + colBase + wc * 32 + j * 16,
                hc, N, wmma::mem_row_major);
        }
}

// ------- fused scale + mask + softmax over all 4 g + final_graph, per row -------
__global__ void softmax_fg_kernel(__half* __restrict__ Ah, const float* __restrict__ foot,
                                  float* __restrict__ fg) {
    int n = blockIdx.x;
    int tid = threadIdx.x;
    __shared__ float red8[8];
    float frx = foot[2 * n], fry = foot[2 * n + 1];

    unsigned mask = 0;
    #pragma unroll
    for (int i = 0; i < 8; i++) {
        int c = 2 * (tid + i * 256);
        float dx0 = frx - foot[2 * c],     dy0 = fry - foot[2 * c + 1];
        float dx1 = frx - foot[2 * c + 2], dy1 = fry - foot[2 * c + 3];
        if (dx0 * dx0 + dy0 * dy0 > THR2) mask |= (1u << (2 * i));
        if (dx1 * dx1 + dy1 * dy1 > THR2) mask |= (1u << (2 * i + 1));
    }

    float fgx[8], fgy[8];
    #pragma unroll
    for (int i = 0; i < 8; i++) { fgx[i] = 0.f; fgy[i] = 0.f; }

    for (int g = 0; g < NG_; g++) {
        __half2* row2 = (__half2*)(Ah + ((long long)g * NB + n) * NB);
        float v0[8], v1[8];
        float m = -INFINITY;
        #pragma unroll
        for (int i = 0; i < 8; i++) {
            float2 s = __half22float2(row2[tid + i * 256]);
            v0[i] = (mask & (1u << (2 * i)))     ? -INFINITY : s.x * SIMSCALE;
            v1[i] = (mask & (1u << (2 * i + 1))) ? -INFINITY : s.y * SIMSCALE;
            m = fmaxf(m, fmaxf(v0[i], v1[i]));
        }
        m = block_reduce_256<0>(m, red8, tid);
        float sum = 0.0f;
        #pragma unroll
        for (int i = 0; i < 8; i++) {
            v0[i] = __expf(v0[i] - m); v1[i] = __expf(v1[i] - m);
            sum += v0[i] + v1[i];
        }
        sum = block_reduce_256<1>(sum, red8, tid);
        float inv = 1.0f / sum;
        #pragma unroll
        for (int i = 0; i < 8; i++) {
            float a0 = v0[i] * inv, a1 = v1[i] * inv;
            row2[tid + i * 256] = __floats2half2_rn(a0, a1);
            fgx[i] += a0; fgy[i] += a1;
        }
    }

    float2* fg2 = (float2*)(fg + (long long)n * NB);
    #pragma unroll
    for (int i = 0; i < 8; i++) {
        float2 r;
        r.x = fminf(0.25f * fgx[i], 1.0f);
        r.y = fminf(0.25f * fgy[i], 1.0f);
        fg2[tid + i * 256] = r;
    }
}

// ---------------- LayerNorm + ReLU + sum over g (fp16 input) ----------------
__global__ void ln_kernel(const __half* __restrict__ outp,
                          const float* __restrict__ gamma,
                          const float* __restrict__ beta,
                          float* __restrict__ out) {
    int n = blockIdx.x;
    int tid = threadIdx.x;  // 256
    __shared__ float red8[8];
    float accum[4] = {0.f, 0.f, 0.f, 0.f};
    for (int g = 0; g < NG_; g++) {
        const __half2* row2 = (const __half2*)(outp + ((long long)g * NB + n) * NFG_);
        float v[4];
        {
            float2 a = __half22float2(row2[tid]);
            float2 b = __half22float2(row2[tid + 256]);
            v[0] = a.x; v[1] = a.y; v[2] = b.x; v[3] = b.y;
        }
        float s = v[0] + v[1] + v[2] + v[3];
        float tot = block_reduce_256<1>(s, red8, tid);
        float mean = tot * (1.0f / NFG_);
        float s2 = 0.0f;
        #pragma unroll
        for (int i = 0; i < 4; i++) { float d = v[i] - mean; s2 += d * d; }
        float var = block_reduce_256<1>(s2, red8, tid);
        float inv = rsqrtf(var * (1.0f / NFG_) + 1e-5f);
        {
            int c0 = 2 * tid, c1 = 2 * (tid + 256);
            const float* ga = gamma + g * NFG_;
            const float* be = beta + g * NFG_;
            accum[0] += fmaxf((v[0] - mean) * inv * ga[c0]     + be[c0],     0.0f);
            accum[1] += fmaxf((v[1] - mean) * inv * ga[c0 + 1] + be[c0 + 1], 0.0f);
            accum[2] += fmaxf((v[2] - mean) * inv * ga[c1]     + be[c1],     0.0f);
            accum[3] += fmaxf((v[3] - mean) * inv * ga[c1 + 1] + be[c1 + 1], 0.0f);
        }
    }
    float* orow = out + (long long)n * NFG_;
    *(float2*)(orow + 2 * tid)         = make_float2(accum[0], accum[1]);
    *(float2*)(orow + 2 * (tid + 256)) = make_float2(accum[2], accum[3]);
}

// ======================= launch =======================
extern "C" void kernel_launch(void* const* d_in, const int* in_sizes, int n_in,
                              void* d_out, int out_size) {
    const float* feats   = (const float*)d_in[0];
    const float* boxes   = (const float*)d_in[1];
    const float* theta_w = (const float*)d_in[2];
    const float* theta_b = (const float*)d_in[3];
    const float* phi_w   = (const float*)d_in[4];
    const float* phi_b   = (const float*)d_in[5];
    const float* gcn_w   = (const float*)d_in[6];
    const float* ln_g    = (const float*)d_in[7];
    const float* ln_b    = (const float*)d_in[8];
    float* out = (float*)d_out;   // [4096*1024] out ++ [4096*4096] final_graph

    float *p_foot;
    __half *p_fpp, *p_thW, *p_phW, *p_gwW, *p_ft, *p_theta, *p_phi, *p_Ah, *p_agg, *p_outp;
    cudaGetSymbolAddress((void**)&p_foot, g_foot);
    cudaGetSymbolAddress((void**)&p_fpp,  g_fpp_h);
    cudaGetSymbolAddress((void**)&p_thW,  g_thW_h);
    cudaGetSymbolAddress((void**)&p_phW,  g_phW_h);
    cudaGetSymbolAddress((void**)&p_gwW,  g_gwW_h);
    cudaGetSymbolAddress((void**)&p_ft,   g_ft_h);
    cudaGetSymbolAddress((void**)&p_theta, g_theta_h);
    cudaGetSymbolAddress((void**)&p_phi,  g_phi_h);
    cudaGetSymbolAddress((void**)&p_Ah,   g_A_h);
    cudaGetSymbolAddress((void**)&p_agg,  g_agg_h);
    cudaGetSymbolAddress((void**)&p_outp, g_outp_h);

    cudaFuncSetAttribute(hgemm_kernel<0,1>, cudaFuncAttributeMaxDynamicSharedMemorySize, SMEM_NT);
    cudaFuncSetAttribute(hgemm_kernel<0,0>, cudaFuncAttributeMaxDynamicSharedMemorySize, SMEM_NT);
    cudaFuncSetAttribute(hgemm_kernel<1,0>, cudaFuncAttributeMaxDynamicSharedMemorySize, SMEM_T);

    // 1) foot + fpp(fp16)
    foot_kernel<<<(NB + 255) / 256, 256>>>(boxes, p_foot);
    long long fppN = (long long)NB * FPPD;
    fpp_kernel<<<(unsigned)((fppN + 255) / 256), 256>>>(feats, p_foot, p_fpp);

    // 2) fp16 operand conversions
    {
        long long nw = (long long)NG_ * FPPD * NFR_;
        conv_kernel<<<(unsigned)(nw / 4 / 256), 256>>>(theta_w, p_thW, nw);
        conv_kernel<<<(unsigned)(nw / 4 / 256), 256>>>(phi_w, p_phW, nw);
        long long ng = (long long)NG_ * NFG_ * NFG_;
        conv_kernel<<<(unsigned)(ng / 4 / 256), 256>>>(gcn_w, p_gwW, ng);
        long long nf = (long long)NB * NFG_;
        conv_kernel<<<(unsigned)(nf / 4 / 256), 256>>>(feats, p_ft, nf);
    }

    // 3) theta/phi GEMMs -> fp16 with fused bias epilogue
    {
        dim3 grid(NFR_ / GBN, NB / GBM, NG_);   // (2, 32, 4)
        hgemm_kernel<0,1><<<grid, 256, SMEM_NT>>>(p_fpp, p_thW, p_theta, theta_b,
                                                  NB, NFR_, FPPD,
                                                  0, (long long)FPPD * NFR_, (long long)NB * NFR_);
        hgemm_kernel<0,1><<<grid, 256, SMEM_NT>>>(p_fpp, p_phW, p_phi, phi_b,
                                                  NB, NFR_, FPPD,
                                                  0, (long long)FPPD * NFR_, (long long)NB * NFR_);
    }

    // 4) sim = theta @ phi^T -> fp16 directly into A buffer
    {
        dim3 grid(NB / GBN, NB / GBM, NG_);     // (32, 32, 4)
        hgemm_kernel<1,0><<<grid, 256, SMEM_T>>>(p_theta, p_phi, p_Ah, nullptr,
                                                 NB, NB, NFR_,
                                                 (long long)NB * NFR_, (long long)NB * NFR_,
                                                 (long long)NB * NB);
    }

    // 5) softmax over all g + final_graph (fused), fp16 A in-place
    softmax_fg_kernel<<<NB, 256>>>(p_Ah, p_foot, out + (long long)NB * NFG_);

    // 6) agg = A @ feats -> fp16
    {
        dim3 grid(NFG_ / GBN, NB / GBM, NG_);   // (8, 32, 4)
        hgemm_kernel<0,0><<<grid, 256, SMEM_NT>>>(p_Ah, p_ft, p_agg, nullptr,
                                                  NB, NFG_, NB,
                                                  (long long)NB * NB, 0, (long long)NB * NFG_);
    }

    // 7) outp = agg @ gcn_w -> fp16
    {
        dim3 grid(NFG_ / GBN, NB / GBM, NG_);   // (8, 32, 4)
        hgemm_kernel<0,0><<<grid, 256, SMEM_NT>>>(p_agg, p_gwW, p_outp, nullptr,
                                                  NB, NFG_, NFG_,
                                                  (long long)NB * NFG_, (long long)NFG_ * NFG_,
                                                  (long long)NB * NFG_);
    }

    // 8) LN + ReLU + sum over g
    ln_kernel<<<NB, 256>>>(p_outp, ln_g, ln_b, out);
}